// round 7
// baseline (speedup 1.0000x reference)
#include <cuda_runtime.h>
#include <cuda_bf16.h>
#include <mma.h>
#include <stdint.h>

using namespace nvcuda;

#define NN    50000
#define NNP   50048          // padded to 128-row tiles
#define HID   128
#define NREL  3
#define EMAX  800000

// ---------------- scratch (device globals) -----------------------------------
__device__ __align__(16) float g_h  [(size_t)NNP * HID];
__device__ __align__(16) float g_hw [NREL][(size_t)NNP * HID];
__device__ __align__(16) float g_tmp[(size_t)NNP * 64];
__device__ __align__(16) float g_dis[NREL][NN];
__device__ __align__(16) int   g_deg[NREL][NN];
__device__ __align__(16) int   g_off[NREL][NN + 1];
__device__ __align__(16) int   g_cur[NREL][NN];
__device__ __align__(16) int   g_csr[NREL][EMAX];

// ---------------- CSR build ---------------------------------------------------
__global__ void zero_deg_kernel() {
    int i = blockIdx.x * blockDim.x + threadIdx.x;
    if (i < NREL * NN) ((int*)g_deg)[i] = 0;
}

__global__ void count_kernel(const int* __restrict__ edges, int E) {
    const int r = blockIdx.y;
    const int* dst = edges + (size_t)(2 * r + 1) * E;
    for (int e = blockIdx.x * blockDim.x + threadIdx.x; e < E;
         e += gridDim.x * blockDim.x) {
        int d = dst[e];
        if ((unsigned)d < NN) atomicAdd(&g_deg[r][d], 1);
    }
}

__global__ __launch_bounds__(1024) void scan_kernel() {
    const int r = blockIdx.x;
    __shared__ int warp_sums[32];
    __shared__ int s_carry;
    if (threadIdx.x == 0) s_carry = 0;
    __syncthreads();
    const int lane = threadIdx.x & 31;
    const int wid  = threadIdx.x >> 5;
    for (int base = 0; base < NN; base += 1024) {
        int i = base + (int)threadIdx.x;
        int v = (i < NN) ? g_deg[r][i] : 0;
        int x = v;
#pragma unroll
        for (int o = 1; o < 32; o <<= 1) {
            int y = __shfl_up_sync(0xffffffffu, x, o);
            if (lane >= o) x += y;
        }
        if (lane == 31) warp_sums[wid] = x;
        __syncthreads();
        if (threadIdx.x < 32) {
            int w = warp_sums[threadIdx.x];
#pragma unroll
            for (int o = 1; o < 32; o <<= 1) {
                int y = __shfl_up_sync(0xffffffffu, w, o);
                if ((int)threadIdx.x >= o) w += y;
            }
            warp_sums[threadIdx.x] = w;
        }
        __syncthreads();
        int incl = x + (wid > 0 ? warp_sums[wid - 1] : 0);
        int excl = incl - v + s_carry;
        if (i < NN) { g_off[r][i] = excl; g_cur[r][i] = excl; }
        int block_total = warp_sums[31];
        __syncthreads();
        if (threadIdx.x == 0) s_carry += block_total;
        __syncthreads();
    }
    if (threadIdx.x == 0) g_off[r][NN] = s_carry;
}

__global__ void dis_kernel() {
    int i = blockIdx.x * blockDim.x + threadIdx.x;
    if (i < NREL * NN) {
        int c = ((const int*)g_deg)[i];
        ((float*)g_dis)[i] = rsqrtf((float)c + 1.0f);
    }
}

__global__ void fill_csr_kernel(const int* __restrict__ edges, int E) {
    const int r = blockIdx.y;
    const int* src = edges + (size_t)(2 * r) * E;
    const int* dst = src + E;
    for (int e = blockIdx.x * blockDim.x + threadIdx.x; e < E;
         e += gridDim.x * blockDim.x) {
        int s = src[e], d = dst[e];
        if ((unsigned)d < NN && (unsigned)s < NN) {
            int pos = atomicAdd(&g_cur[r][d], 1);
            g_csr[r][pos] = s;
        }
    }
}

// ---------------- bf16x3 WMMA GEMM --------------------------------------------
// C[128 x NDIM] per block = A @ B via 3-term bf16 split (fp32 accumulate).
// MODE 0: g_h   = Aext @ B  (bias folded at k==K via ones-column; relu later)
// MODE 1: g_hw[r] = diag(dis_r) * g_h @ B[r]   (dis folded into A rows)
// MODE 2: g_tmp = g_h @ B  (bias folded; copied to d_out later)
template <int NDIM, int MODE>
__launch_bounds__(256)
__global__ void wmma_gemm(const float* __restrict__ Aext,
                          const float* __restrict__ Bg,
                          const float* __restrict__ bias,
                          int M, int K, int nch) {
    constexpr int WARPS_N = NDIM / 64;       // 2 for 128, 1 for 64
    constexpr int WARPS_M = 8 / WARPS_N;     // 4 or 8
    constexpr int MT = 128 / (16 * WARPS_M); // row tiles per warp: 2 or 1
    constexpr int LDA = 40;                  // bf16 elems (80B rows, 16B mult)
    constexpr int LDB = NDIM + 8;            // 272B or 144B rows

    __shared__ __nv_bfloat16 sAhi[128][LDA];
    __shared__ __nv_bfloat16 sAlo[128][LDA];
    __shared__ __nv_bfloat16 sBhi[32][LDB];
    __shared__ __nv_bfloat16 sBlo[32][LDB];

    const int r = blockIdx.y;
    const float* A = (MODE == 0) ? Aext : g_h;
    const float* B = Bg + (size_t)r * K * NDIM;

    const int tid = threadIdx.x;
    const int wid = tid >> 5;
    const int wm = wid / WARPS_N;
    const int wn = wid % WARPS_N;
    const int rowBase = blockIdx.x * 128;

    wmma::fragment<wmma::accumulator, 16, 16, 16, float> acc[MT][4];
#pragma unroll
    for (int i = 0; i < MT; i++)
#pragma unroll
        for (int j = 0; j < 4; j++) wmma::fill_fragment(acc[i][j], 0.f);

    for (int ch = 0; ch < nch; ch++) {
        const int k0 = ch * 32;
        // ---- A tile 128 x 32 ----
        for (int e = tid; e < 128 * 32; e += 256) {
            int row = e >> 5, col = e & 31;
            int k = k0 + col;
            int gr = rowBase + row; if (gr >= M) gr = M - 1;
            float v;
            if (k < K)                       v = A[(size_t)gr * K + k];
            else if (MODE != 1 && k == K)    v = 1.f;     // bias fold column
            else                             v = 0.f;
            if (MODE == 1) v *= g_dis[r][gr];             // dis fold (row scale)
            __nv_bfloat16 h = __float2bfloat16(v);
            sAhi[row][col] = h;
            sAlo[row][col] = __float2bfloat16(v - __bfloat162float(h));
        }
        // ---- B tile 32 x NDIM ----
        for (int e = tid; e < 32 * NDIM; e += 256) {
            int row = e / NDIM, col = e % NDIM;
            int k = k0 + row;
            float v;
            if (k < K)                       v = B[(size_t)k * NDIM + col];
            else if (MODE != 1 && k == K)    v = bias[col];   // bias fold row
            else                             v = 0.f;
            __nv_bfloat16 h = __float2bfloat16(v);
            sBhi[row][col] = h;
            sBlo[row][col] = __float2bfloat16(v - __bfloat162float(h));
        }
        __syncthreads();

#pragma unroll
        for (int kk = 0; kk < 32; kk += 16) {
            wmma::fragment<wmma::matrix_a, 16, 16, 16, __nv_bfloat16, wmma::row_major> ahi[MT], alo[MT];
            wmma::fragment<wmma::matrix_b, 16, 16, 16, __nv_bfloat16, wmma::row_major> bhi[4], blo[4];
#pragma unroll
            for (int i = 0; i < MT; i++) {
                wmma::load_matrix_sync(ahi[i], &sAhi[(wm * MT + i) * 16][kk], LDA);
                wmma::load_matrix_sync(alo[i], &sAlo[(wm * MT + i) * 16][kk], LDA);
            }
#pragma unroll
            for (int j = 0; j < 4; j++) {
                wmma::load_matrix_sync(bhi[j], &sBhi[kk][wn * 64 + j * 16], LDB);
                wmma::load_matrix_sync(blo[j], &sBlo[kk][wn * 64 + j * 16], LDB);
            }
#pragma unroll
            for (int i = 0; i < MT; i++)
#pragma unroll
                for (int j = 0; j < 4; j++) {
                    wmma::mma_sync(acc[i][j], ahi[i], bhi[j], acc[i][j]);
                    wmma::mma_sync(acc[i][j], ahi[i], blo[j], acc[i][j]);
                    wmma::mma_sync(acc[i][j], alo[i], bhi[j], acc[i][j]);
                }
        }
        __syncthreads();
    }

    float* Cout = (MODE == 0) ? g_h : (MODE == 1 ? g_hw[r] : g_tmp);
#pragma unroll
    for (int i = 0; i < MT; i++)
#pragma unroll
        for (int j = 0; j < 4; j++) {
            size_t off = (size_t)(rowBase + (wm * MT + i) * 16) * NDIM + wn * 64 + j * 16;
            wmma::store_matrix_sync(&Cout[off], acc[i][j], NDIM, wmma::mem_row_major);
        }
}

// ---------------- small fixups --------------------------------------------------
__global__ void relu_h_kernel() {
    int idx = blockIdx.x * blockDim.x + threadIdx.x;
    const int total = NN * (HID / 4);
    if (idx >= total) return;
    float4 v = ((const float4*)g_h)[idx];
    v.x = fmaxf(v.x, 0.f); v.y = fmaxf(v.y, 0.f);
    v.z = fmaxf(v.z, 0.f); v.w = fmaxf(v.w, 0.f);
    ((float4*)g_h)[idx] = v;
}

__global__ void copy_out_kernel(float* __restrict__ out) {
    int idx = blockIdx.x * blockDim.x + threadIdx.x;
    const int total = NN * (64 / 4);
    if (idx >= total) return;
    ((float4*)out)[idx] = ((const float4*)g_tmp)[idx];
}

// ---------------- CSR gather: warp per node, fused self+bias+relu ------------
__launch_bounds__(256)
__global__ void gather_kernel(const float* __restrict__ bias) {
    const int node = (blockIdx.x * blockDim.x + threadIdx.x) >> 5;
    const int lane = threadIdx.x & 31;
    if (node >= NN) return;
    const int c0 = lane * 4;

    float4 tot;
    tot.x = bias[c0 + 0] + bias[HID + c0 + 0] + bias[2 * HID + c0 + 0];
    tot.y = bias[c0 + 1] + bias[HID + c0 + 1] + bias[2 * HID + c0 + 1];
    tot.z = bias[c0 + 2] + bias[HID + c0 + 2] + bias[2 * HID + c0 + 2];
    tot.w = bias[c0 + 3] + bias[HID + c0 + 3] + bias[2 * HID + c0 + 3];

#pragma unroll
    for (int r = 0; r < NREL; r++) {
        const float4* hw4 = (const float4*)g_hw[r];
        float4 a = hw4[(size_t)node * (HID / 4) + lane];   // self loop (pre-scaled)
        const int beg = g_off[r][node];
        const int end = g_off[r][node + 1];
        const int* __restrict__ csr = g_csr[r];
        for (int t = beg; t < end; t += 32) {
            int idx = (t + lane < end) ? csr[t + lane] : 0;
            int n = end - t; if (n > 32) n = 32;
            for (int j = 0; j < n; j++) {
                int s = __shfl_sync(0xffffffffu, idx, j);
                float4 v = hw4[(size_t)s * (HID / 4) + lane];
                a.x += v.x; a.y += v.y; a.z += v.z; a.w += v.w;
            }
        }
        float dd = g_dis[r][node];
        tot.x += a.x * dd; tot.y += a.y * dd;
        tot.z += a.z * dd; tot.w += a.w * dd;
    }
    tot.x = fmaxf(tot.x, 0.f);
    tot.y = fmaxf(tot.y, 0.f);
    tot.z = fmaxf(tot.z, 0.f);
    tot.w = fmaxf(tot.w, 0.f);
    ((float4*)g_h)[(size_t)node * (HID / 4) + lane] = tot;
}

// ---------------- launch ------------------------------------------------------
extern "C" void kernel_launch(void* const* d_in, const int* in_sizes, int n_in,
                              void* d_out, int out_size) {
    const float* x     = (const float*)d_in[0];
    const int*   ei    = (const int*)d_in[1];   // int32 (JAX x64 disabled)
    const float* emb_w = (const float*)d_in[2];
    const float* emb_b = (const float*)d_in[3];
    const float* w0    = (const float*)d_in[4];
    const float* b0    = (const float*)d_in[5];
    const float* w1    = (const float*)d_in[6];
    const float* b1    = (const float*)d_in[7];
    const float* lin_w = (const float*)d_in[8];
    const float* lin_b = (const float*)d_in[9];
    float* out = (float*)d_out;

    const int E = in_sizes[1] / (2 * NREL);
    const int M = NN;
    const int mtiles = NNP / 128;   // 391

    // CSR build (dis must precede relation GEMMs — fold uses it)
    zero_deg_kernel<<<(NREL * NN + 255) / 256, 256>>>();
    count_kernel<<<dim3(256, NREL), 256>>>(ei, E);
    scan_kernel<<<NREL, 1024>>>();
    dis_kernel<<<(NREL * NN + 255) / 256, 256>>>();
    fill_csr_kernel<<<dim3(256, NREL), 256>>>(ei, E);

    const int gather_blocks = (NN * 32 + 255) / 256;
    const int elem_blocks   = (NN * (HID / 4) + 255) / 256;

    // embedder: h = relu(x @ emb_w + emb_b)   (K=300, pad to 320, bias at k=300)
    wmma_gemm<128, 0><<<dim3(mtiles, 1), 256>>>(x, emb_w, emb_b, M, 300, 10);
    relu_h_kernel<<<elem_blocks, 256>>>();

    // layer 0:  hw[r] = diag(dis_r) h @ w0[r]
    wmma_gemm<128, 1><<<dim3(mtiles, NREL), 256>>>(nullptr, w0, nullptr, M, HID, 4);
    gather_kernel<<<gather_blocks, 256>>>(b0);

    // layer 1
    wmma_gemm<128, 1><<<dim3(mtiles, NREL), 256>>>(nullptr, w1, nullptr, M, HID, 4);
    gather_kernel<<<gather_blocks, 256>>>(b1);

    // final linear: out = h @ lin_w + lin_b   (K=128, pad to 160, bias at k=128)
    wmma_gemm<64, 2><<<dim3(mtiles, 1), 256>>>(nullptr, lin_w, lin_b, M, HID, 5);
    copy_out_kernel<<<(NN * 16 + 255) / 256, 256>>>(out);
}